// round 7
// baseline (speedup 1.0000x reference)
#include <cuda_runtime.h>
#include <math_constants.h>

// Problem constants (fixed shapes from setup_inputs)
#define BB 8
#define LP1 25
#define LL 24
#define TT 512
#define DD 1024
#define PP 128
#define TOPK 3

#define SPLIT1 16   // T-splits for score pass  -> 8*24*16 = 3072 blocks
#define SPLIT3 128  // T-splits for gather pass -> 8*128   = 1024 blocks
#define FBLK   4    // p-slices per batch in k_final -> 32 blocks

// Output layout: flattened tuple in reference order, all fp32
#define OFF_PROJ   0
#define OFF_SCORES 1024
#define OFF_IDX    1216
#define OFF_SEL    1240

// Scratch (device globals; allocation-free)
__device__ float g_score_partial[BB * LL * SPLIT1];
__device__ int   g_topk_idx[BB * TOPK];
__device__ float g_topk_val[BB * TOPK];
__device__ float g_pooled[BB * DD];      // atomic-max accumulator (32 KB)
__device__ int   g_cnt;                  // last-block counter (self-resetting)

// Exact, order-independent float atomic max (bit trick).
__device__ __forceinline__ void atomicMaxFloat(float* addr, float v) {
    if (v >= 0.0f) {
        atomicMax((int*)addr, __float_as_int(v));
    } else {
        atomicMin((unsigned int*)addr, __float_as_uint(v));
    }
}

// ---------------------------------------------------------------------------
// Kernel 1: per-(b,l,s) score partials over 32 t-rows each; first 32 blocks
// also init g_pooled. The LAST block additionally does softmax + top-3.
// ---------------------------------------------------------------------------
__global__ __launch_bounds__(256) void k_scores(const float* __restrict__ x,
                                                const float* __restrict__ w_score,
                                                const float* __restrict__ b_score,
                                                float* __restrict__ out) {
    const int blk = blockIdx.x;           // 0 .. BB*LL*SPLIT1-1
    const int tid = threadIdx.x;

    // init atomic-max accumulator for the gather pass
    if (blk < 32) g_pooled[blk * 256 + tid] = -CUDART_INF_F;

    const int s   = blk % SPLIT1;
    const int bl  = blk / SPLIT1;
    const int l   = bl % LL;
    const int b   = bl / LL;

    const float4* __restrict__ base =
        (const float4*)(x + ((size_t)b * LP1 + (size_t)(l + 1)) * TT * DD);
    const float4 w4 = ((const float4*)w_score)[tid];

    float acc = 0.f;
    const int t0 = s * (TT / SPLIT1);     // 32 rows per block
    #pragma unroll 8
    for (int t = t0; t < t0 + TT / SPLIT1; ++t) {
        float4 v = base[(size_t)t * (DD / 4) + tid];
        acc += v.x * w4.x + v.y * w4.y + v.z * w4.z + v.w * w4.w;
    }

    __shared__ float sm[256];
    sm[tid] = acc;
    __syncthreads();
    #pragma unroll
    for (int st = 128; st > 0; st >>= 1) {
        if (tid < st) sm[tid] += sm[tid + st];
        __syncthreads();
    }

    // publish partial, then last-block detection
    __shared__ int s_last;
    if (tid == 0) {
        g_score_partial[bl * SPLIT1 + s] = sm[0];
        __threadfence();
        int old = atomicAdd(&g_cnt, 1);
        s_last = (old == BB * LL * SPLIT1 - 1);
    }
    __syncthreads();
    if (!s_last) return;

    // ---- fused top-k (runs in exactly one block, after all partials) ----
    __threadfence();
    __shared__ float sc[BB * LL];
    if (tid < BB * LL) {
        float v = 0.f;
        #pragma unroll
        for (int i = 0; i < SPLIT1; ++i) v += g_score_partial[tid * SPLIT1 + i];
        v = v * (1.0f / (float)TT) + b_score[0];
        sc[tid] = v;
        out[OFF_SCORES + tid] = v;
    }
    __syncthreads();

    if (tid < BB) {
        const int bb = tid;
        float m = -CUDART_INF_F;
        #pragma unroll
        for (int l2 = 0; l2 < LL; ++l2) m = fmaxf(m, sc[bb * LL + l2]);
        float p[LL];
        float sum = 0.f;
        #pragma unroll
        for (int l2 = 0; l2 < LL; ++l2) { p[l2] = expf(sc[bb * LL + l2] - m); sum += p[l2]; }
        const float inv = 1.0f / sum;
        #pragma unroll
        for (int l2 = 0; l2 < LL; ++l2) p[l2] *= inv;

        bool used[LL];
        #pragma unroll
        for (int l2 = 0; l2 < LL; ++l2) used[l2] = false;

        for (int k = 0; k < TOPK; ++k) {
            int   best = 0;
            float bv   = -CUDART_INF_F;
            #pragma unroll
            for (int l2 = 0; l2 < LL; ++l2) {
                if (!used[l2] && p[l2] > bv) { bv = p[l2]; best = l2; }
            }
            used[best] = true;
            g_topk_idx[bb * TOPK + k] = best;
            g_topk_val[bb * TOPK + k] = bv;
            out[OFF_IDX + bb * TOPK + k] = (float)best;
        }
    }
    // reset counter for the next graph replay (deterministic)
    if (tid == 0) g_cnt = 0;
}

// ---------------------------------------------------------------------------
// Kernel 3: gather 3 selected layers. FRONT-BATCHED: all 12 float4 loads
// issued before any store/compute (MLP=12/thread), then 12 streaming stores,
// then weighted-sum + max + 4 REDG-max.
// ---------------------------------------------------------------------------
__global__ __launch_bounds__(256) void k_gather(const float* __restrict__ x,
                                                float* __restrict__ out) {
    const int blk = blockIdx.x;             // 0 .. BB*SPLIT3-1
    const int s   = blk % SPLIT3;
    const int b   = blk / SPLIT3;
    const int tid = threadIdx.x;

    const int i0 = g_topk_idx[b * TOPK + 0];
    const int i1 = g_topk_idx[b * TOPK + 1];
    const int i2 = g_topk_idx[b * TOPK + 2];
    const float v0 = g_topk_val[b * TOPK + 0];
    const float v1 = g_topk_val[b * TOPK + 1];
    const float v2 = g_topk_val[b * TOPK + 2];

    const float4* __restrict__ p0 =
        (const float4*)(x + ((size_t)b * LP1 + (size_t)(i0 + 1)) * TT * DD);
    const float4* __restrict__ p1 =
        (const float4*)(x + ((size_t)b * LP1 + (size_t)(i1 + 1)) * TT * DD);
    const float4* __restrict__ p2 =
        (const float4*)(x + ((size_t)b * LP1 + (size_t)(i2 + 1)) * TT * DD);

    float* __restrict__ sel = out + OFF_SEL;
    float4* __restrict__ o0 = (float4*)(sel + ((size_t)b * TOPK + 0) * TT * DD);
    float4* __restrict__ o1 = (float4*)(sel + ((size_t)b * TOPK + 1) * TT * DD);
    float4* __restrict__ o2 = (float4*)(sel + ((size_t)b * TOPK + 2) * TT * DD);

    const int TPS = TT / SPLIT3;   // 4 rows per block

    size_t off[TPS];
    #pragma unroll
    for (int tt = 0; tt < TPS; ++tt)
        off[tt] = (size_t)(s * TPS + tt) * (DD / 4) + tid;

    // --- front-batched loads: 12 independent LDG.128 in flight ---
    float4 a[TPS], c[TPS], e[TPS];
    #pragma unroll
    for (int tt = 0; tt < TPS; ++tt) a[tt] = p0[off[tt]];
    #pragma unroll
    for (int tt = 0; tt < TPS; ++tt) c[tt] = p1[off[tt]];
    #pragma unroll
    for (int tt = 0; tt < TPS; ++tt) e[tt] = p2[off[tt]];

    // --- streaming stores ---
    #pragma unroll
    for (int tt = 0; tt < TPS; ++tt) __stcs(&o0[off[tt]], a[tt]);
    #pragma unroll
    for (int tt = 0; tt < TPS; ++tt) __stcs(&o1[off[tt]], c[tt]);
    #pragma unroll
    for (int tt = 0; tt < TPS; ++tt) __stcs(&o2[off[tt]], e[tt]);

    // --- weighted sum + max over the 4 rows ---
    float4 mx = make_float4(-CUDART_INF_F, -CUDART_INF_F, -CUDART_INF_F, -CUDART_INF_F);
    #pragma unroll
    for (int tt = 0; tt < TPS; ++tt) {
        float4 w;
        w.x = v0 * a[tt].x + v1 * c[tt].x + v2 * e[tt].x;
        w.y = v0 * a[tt].y + v1 * c[tt].y + v2 * e[tt].y;
        w.z = v0 * a[tt].z + v1 * c[tt].z + v2 * e[tt].z;
        w.w = v0 * a[tt].w + v1 * c[tt].w + v2 * e[tt].w;
        mx.x = fmaxf(mx.x, w.x);
        mx.y = fmaxf(mx.y, w.y);
        mx.z = fmaxf(mx.z, w.z);
        mx.w = fmaxf(mx.w, w.w);
    }

    float* gp = g_pooled + (size_t)b * DD + tid * 4;
    atomicMaxFloat(gp + 0, mx.x);
    atomicMaxFloat(gp + 1, mx.y);
    atomicMaxFloat(gp + 2, mx.z);
    atomicMaxFloat(gp + 3, mx.w);
}

// ---------------------------------------------------------------------------
// Kernel 4: grid = BB*FBLK, block = 1024.
// LN over g_pooled[b], then a 32-output GEMV slice: warp w covers
// d in [32w, 32w+32) fully unrolled (MLP ~32 vs DRAM latency).
// ---------------------------------------------------------------------------
__global__ __launch_bounds__(1024) void k_final(const float* __restrict__ gamma,
                                                const float* __restrict__ beta,
                                                const float* __restrict__ w_proj,
                                                const float* __restrict__ b_proj,
                                                float* __restrict__ out) {
    const int b    = blockIdx.x >> 2;     // FBLK = 4
    const int pb   = blockIdx.x & 3;
    const int tid  = threadIdx.x;
    const int lane = tid & 31, warp = tid >> 5;

    __shared__ float normed[DD];
    __shared__ float red[32], red2[32];
    __shared__ float s_stats[2];
    __shared__ float part[1024];

    const float m = g_pooled[(size_t)b * DD + tid];

    // LN stats
    {
        float s1 = m, s2 = m * m;
        #pragma unroll
        for (int o = 16; o > 0; o >>= 1) {
            s1 += __shfl_down_sync(0xffffffffu, s1, o);
            s2 += __shfl_down_sync(0xffffffffu, s2, o);
        }
        if (lane == 0) { red[warp] = s1; red2[warp] = s2; }
    }
    __syncthreads();
    if (tid < 32) {
        float s1 = red[tid], s2 = red2[tid];
        #pragma unroll
        for (int o = 16; o > 0; o >>= 1) {
            s1 += __shfl_down_sync(0xffffffffu, s1, o);
            s2 += __shfl_down_sync(0xffffffffu, s2, o);
        }
        if (tid == 0) {
            float mu  = s1 * (1.0f / (float)DD);
            float var = s2 * (1.0f / (float)DD) - mu * mu;
            s_stats[0] = mu;
            s_stats[1] = rsqrtf(var + 1e-5f);
        }
    }
    __syncthreads();

    normed[tid] = (m - s_stats[0]) * s_stats[1] * gamma[tid] + beta[tid];
    __syncthreads();

    // GEMV slice: output p = pb*32 + lane; warp covers 32 d's, fully unrolled.
    {
        const int p  = pb * 32 + lane;
        const int d0 = warp * 32;
        const float* __restrict__ wp = w_proj + (size_t)d0 * PP + p;
        float acc = 0.f;
        #pragma unroll
        for (int i = 0; i < 32; ++i)
            acc = fmaf(normed[d0 + i], wp[(size_t)i * PP], acc);
        part[tid] = acc;
    }
    __syncthreads();
    if (tid < 32) {
        const int p = pb * 32 + tid;
        float acc = b_proj[p];
        #pragma unroll
        for (int c = 0; c < 32; ++c) acc += part[c * 32 + tid];
        out[OFF_PROJ + b * PP + p] = acc;
    }
}

// ---------------------------------------------------------------------------
// Launch
// ---------------------------------------------------------------------------
extern "C" void kernel_launch(void* const* d_in, const int* in_sizes, int n_in,
                              void* d_out, int out_size) {
    const float* x       = (const float*)d_in[0];  // wav2vec_ft (8,25,512,1024)
    const float* w_score = (const float*)d_in[1];  // (1024,1)
    const float* b_score = (const float*)d_in[2];  // (1,)
    const float* ln_g    = (const float*)d_in[3];  // (1024,)
    const float* ln_b    = (const float*)d_in[4];  // (1024,)
    const float* w_proj  = (const float*)d_in[5];  // (1024,128)
    const float* b_proj  = (const float*)d_in[6];  // (128,)
    float* out = (float*)d_out;

    k_scores<<<BB * LL * SPLIT1, 256>>>(x, w_score, b_score, out);
    k_gather<<<BB * SPLIT3, 256>>>(x, out);
    k_final<<<BB * FBLK, 1024>>>(ln_g, ln_b, w_proj, b_proj, out);
}

// round 8
// speedup vs baseline: 1.0520x; 1.0520x over previous
#include <cuda_runtime.h>
#include <math_constants.h>

// Problem constants (fixed shapes from setup_inputs)
#define BB 8
#define LP1 25
#define LL 24
#define TT 512
#define DD 1024
#define PP 128
#define TOPK 3

#define SPLIT1 16   // T-splits for score pass  -> 8*24*16 = 3072 blocks
#define SPLIT3 64   // T-splits for gather pass -> 8*64    = 512 blocks
#define FBLK   4    // p-slices per batch in k_final -> 32 blocks

// Output layout: flattened tuple in reference order, all fp32
#define OFF_PROJ   0
#define OFF_SCORES 1024
#define OFF_IDX    1216
#define OFF_SEL    1240

// Scratch (device globals; allocation-free)
__device__ float g_score_partial[BB * LL * SPLIT1];
__device__ int   g_topk_idx[BB * TOPK];
__device__ float g_topk_val[BB * TOPK];
__device__ float g_pooled[BB * DD];      // atomic-max accumulator (32 KB)
__device__ int   g_cnt;                  // last-block counter (self-resetting)

// Exact, order-independent float atomic max (bit trick).
__device__ __forceinline__ void atomicMaxFloat(float* addr, float v) {
    if (v >= 0.0f) {
        atomicMax((int*)addr, __float_as_int(v));
    } else {
        atomicMin((unsigned int*)addr, __float_as_uint(v));
    }
}

// ---------------------------------------------------------------------------
// Kernel 1: per-(b,l,s) score partials over 32 t-rows each; first 32 blocks
// also init g_pooled. The LAST block additionally does softmax + top-3.
// ---------------------------------------------------------------------------
__global__ __launch_bounds__(256) void k_scores(const float* __restrict__ x,
                                                const float* __restrict__ w_score,
                                                const float* __restrict__ b_score,
                                                float* __restrict__ out) {
    const int blk = blockIdx.x;           // 0 .. BB*LL*SPLIT1-1
    const int tid = threadIdx.x;

    // init atomic-max accumulator for the gather pass
    if (blk < 32) g_pooled[blk * 256 + tid] = -CUDART_INF_F;

    const int s   = blk % SPLIT1;
    const int bl  = blk / SPLIT1;
    const int l   = bl % LL;
    const int b   = bl / LL;

    const float4* __restrict__ base =
        (const float4*)(x + ((size_t)b * LP1 + (size_t)(l + 1)) * TT * DD);
    const float4 w4 = ((const float4*)w_score)[tid];

    float acc = 0.f;
    const int t0 = s * (TT / SPLIT1);     // 32 rows per block
    #pragma unroll 8
    for (int t = t0; t < t0 + TT / SPLIT1; ++t) {
        float4 v = base[(size_t)t * (DD / 4) + tid];
        acc += v.x * w4.x + v.y * w4.y + v.z * w4.z + v.w * w4.w;
    }

    __shared__ float sm[256];
    sm[tid] = acc;
    __syncthreads();
    #pragma unroll
    for (int st = 128; st > 0; st >>= 1) {
        if (tid < st) sm[tid] += sm[tid + st];
        __syncthreads();
    }

    // publish partial, then last-block detection
    __shared__ int s_last;
    if (tid == 0) {
        g_score_partial[bl * SPLIT1 + s] = sm[0];
        __threadfence();
        int old = atomicAdd(&g_cnt, 1);
        s_last = (old == BB * LL * SPLIT1 - 1);
    }
    __syncthreads();
    if (!s_last) return;

    // ---- fused top-k (runs in exactly one block, after all partials) ----
    __threadfence();
    __shared__ float sc[BB * LL];
    if (tid < BB * LL) {
        float v = 0.f;
        #pragma unroll
        for (int i = 0; i < SPLIT1; ++i) v += g_score_partial[tid * SPLIT1 + i];
        v = v * (1.0f / (float)TT) + b_score[0];
        sc[tid] = v;
        out[OFF_SCORES + tid] = v;
    }
    __syncthreads();

    if (tid < BB) {
        const int bb = tid;
        float m = -CUDART_INF_F;
        #pragma unroll
        for (int l2 = 0; l2 < LL; ++l2) m = fmaxf(m, sc[bb * LL + l2]);
        float p[LL];
        float sum = 0.f;
        #pragma unroll
        for (int l2 = 0; l2 < LL; ++l2) { p[l2] = expf(sc[bb * LL + l2] - m); sum += p[l2]; }
        const float inv = 1.0f / sum;
        #pragma unroll
        for (int l2 = 0; l2 < LL; ++l2) p[l2] *= inv;

        bool used[LL];
        #pragma unroll
        for (int l2 = 0; l2 < LL; ++l2) used[l2] = false;

        for (int k = 0; k < TOPK; ++k) {
            int   best = 0;
            float bv   = -CUDART_INF_F;
            #pragma unroll
            for (int l2 = 0; l2 < LL; ++l2) {
                if (!used[l2] && p[l2] > bv) { bv = p[l2]; best = l2; }
            }
            used[best] = true;
            g_topk_idx[bb * TOPK + k] = best;
            g_topk_val[bb * TOPK + k] = bv;
            out[OFF_IDX + bb * TOPK + k] = (float)best;
        }
    }
    // reset counter for the next graph replay (deterministic)
    if (tid == 0) g_cnt = 0;
}

// ---------------------------------------------------------------------------
// Kernel 3: gather 3 selected layers -> write selected_layers output
// (streaming stores), fused weighted sum + block-local max over T, then
// exact atomic max into g_pooled. Interleaved loop, 8 t-rows per block.
// ---------------------------------------------------------------------------
__global__ __launch_bounds__(256) void k_gather(const float* __restrict__ x,
                                                float* __restrict__ out) {
    const int blk = blockIdx.x;             // 0 .. BB*SPLIT3-1
    const int s   = blk % SPLIT3;
    const int b   = blk / SPLIT3;
    const int tid = threadIdx.x;

    const int i0 = g_topk_idx[b * TOPK + 0];
    const int i1 = g_topk_idx[b * TOPK + 1];
    const int i2 = g_topk_idx[b * TOPK + 2];
    const float v0 = g_topk_val[b * TOPK + 0];
    const float v1 = g_topk_val[b * TOPK + 1];
    const float v2 = g_topk_val[b * TOPK + 2];

    const float4* __restrict__ p0 =
        (const float4*)(x + ((size_t)b * LP1 + (size_t)(i0 + 1)) * TT * DD);
    const float4* __restrict__ p1 =
        (const float4*)(x + ((size_t)b * LP1 + (size_t)(i1 + 1)) * TT * DD);
    const float4* __restrict__ p2 =
        (const float4*)(x + ((size_t)b * LP1 + (size_t)(i2 + 1)) * TT * DD);

    float* __restrict__ sel = out + OFF_SEL;
    float4* __restrict__ o0 = (float4*)(sel + ((size_t)b * TOPK + 0) * TT * DD);
    float4* __restrict__ o1 = (float4*)(sel + ((size_t)b * TOPK + 1) * TT * DD);
    float4* __restrict__ o2 = (float4*)(sel + ((size_t)b * TOPK + 2) * TT * DD);

    const int TPS = TT / SPLIT3;   // 8 rows per block
    float4 mx = make_float4(-CUDART_INF_F, -CUDART_INF_F, -CUDART_INF_F, -CUDART_INF_F);

    #pragma unroll
    for (int tt = 0; tt < TPS; ++tt) {
        const size_t off = (size_t)(s * TPS + tt) * (DD / 4) + tid;
        float4 a = p0[off];
        float4 c = p1[off];
        float4 e = p2[off];
        __stcs(&o0[off], a);
        __stcs(&o1[off], c);
        __stcs(&o2[off], e);
        float4 w;
        w.x = v0 * a.x + v1 * c.x + v2 * e.x;
        w.y = v0 * a.y + v1 * c.y + v2 * e.y;
        w.z = v0 * a.z + v1 * c.z + v2 * e.z;
        w.w = v0 * a.w + v1 * c.w + v2 * e.w;
        mx.x = fmaxf(mx.x, w.x);
        mx.y = fmaxf(mx.y, w.y);
        mx.z = fmaxf(mx.z, w.z);
        mx.w = fmaxf(mx.w, w.w);
    }

    float* gp = g_pooled + (size_t)b * DD + tid * 4;
    atomicMaxFloat(gp + 0, mx.x);
    atomicMaxFloat(gp + 1, mx.y);
    atomicMaxFloat(gp + 2, mx.z);
    atomicMaxFloat(gp + 3, mx.w);
}

// ---------------------------------------------------------------------------
// Kernel 4: grid = BB*FBLK, block = 1024.
// LN over g_pooled[b], then a 32-output GEMV slice: warp w covers
// d in [32w, 32w+32) fully unrolled (MLP ~32 vs DRAM latency).
// ---------------------------------------------------------------------------
__global__ __launch_bounds__(1024) void k_final(const float* __restrict__ gamma,
                                                const float* __restrict__ beta,
                                                const float* __restrict__ w_proj,
                                                const float* __restrict__ b_proj,
                                                float* __restrict__ out) {
    const int b    = blockIdx.x >> 2;     // FBLK = 4
    const int pb   = blockIdx.x & 3;
    const int tid  = threadIdx.x;
    const int lane = tid & 31, warp = tid >> 5;

    __shared__ float normed[DD];
    __shared__ float red[32], red2[32];
    __shared__ float s_stats[2];
    __shared__ float part[1024];

    const float m = g_pooled[(size_t)b * DD + tid];

    // LN stats
    {
        float s1 = m, s2 = m * m;
        #pragma unroll
        for (int o = 16; o > 0; o >>= 1) {
            s1 += __shfl_down_sync(0xffffffffu, s1, o);
            s2 += __shfl_down_sync(0xffffffffu, s2, o);
        }
        if (lane == 0) { red[warp] = s1; red2[warp] = s2; }
    }
    __syncthreads();
    if (tid < 32) {
        float s1 = red[tid], s2 = red2[tid];
        #pragma unroll
        for (int o = 16; o > 0; o >>= 1) {
            s1 += __shfl_down_sync(0xffffffffu, s1, o);
            s2 += __shfl_down_sync(0xffffffffu, s2, o);
        }
        if (tid == 0) {
            float mu  = s1 * (1.0f / (float)DD);
            float var = s2 * (1.0f / (float)DD) - mu * mu;
            s_stats[0] = mu;
            s_stats[1] = rsqrtf(var + 1e-5f);
        }
    }
    __syncthreads();

    normed[tid] = (m - s_stats[0]) * s_stats[1] * gamma[tid] + beta[tid];
    __syncthreads();

    // GEMV slice: output p = pb*32 + lane; warp covers 32 d's, fully unrolled.
    {
        const int p  = pb * 32 + lane;
        const int d0 = warp * 32;
        const float* __restrict__ wp = w_proj + (size_t)d0 * PP + p;
        float acc = 0.f;
        #pragma unroll
        for (int i = 0; i < 32; ++i)
            acc = fmaf(normed[d0 + i], wp[(size_t)i * PP], acc);
        part[tid] = acc;
    }
    __syncthreads();
    if (tid < 32) {
        const int p = pb * 32 + tid;
        float acc = b_proj[p];
        #pragma unroll
        for (int c = 0; c < 32; ++c) acc += part[c * 32 + tid];
        out[OFF_PROJ + b * PP + p] = acc;
    }
}

// ---------------------------------------------------------------------------
// Launch
// ---------------------------------------------------------------------------
extern "C" void kernel_launch(void* const* d_in, const int* in_sizes, int n_in,
                              void* d_out, int out_size) {
    const float* x       = (const float*)d_in[0];  // wav2vec_ft (8,25,512,1024)
    const float* w_score = (const float*)d_in[1];  // (1024,1)
    const float* b_score = (const float*)d_in[2];  // (1,)
    const float* ln_g    = (const float*)d_in[3];  // (1024,)
    const float* ln_b    = (const float*)d_in[4];  // (1024,)
    const float* w_proj  = (const float*)d_in[5];  // (1024,128)
    const float* b_proj  = (const float*)d_in[6];  // (128,)
    float* out = (float*)d_out;

    k_scores<<<BB * LL * SPLIT1, 256>>>(x, w_score, b_score, out);
    k_gather<<<BB * SPLIT3, 256>>>(x, out);
    k_final<<<BB * FBLK, 1024>>>(ln_g, ln_b, w_proj, b_proj, out);
}